// round 1
// baseline (speedup 1.0000x reference)
#include <cuda_runtime.h>

// SNN recurrence: B=1024, T=1024, H=32 (2 groups x 16), I=2.
// Mapping: one warp per batch, one lane per hidden unit.
// x[b,t,0:2] staged through shared memory (double-buffered), broadcast LDS.
// Non-contracted fp32 arithmetic in reference evaluation order to track the
// JAX fp32 trajectory as closely as possible (spike flips are the risk).

#define TT 1024
#define NB 1024
#define DECISION_CHUNK 24   // t >= 768  <=>  chunk >= 24 (32 steps/chunk)

__global__ __launch_bounds__(128, 8)
void snn_kernel(const float* __restrict__ x,
                const float* __restrict__ Wg,     // [2,16,2] -> flat [32,2]
                const float* __restrict__ tau_g,  // [2,16]   -> flat [32]
                const float* __restrict__ tau_s,  // [32]
                const float* __restrict__ Wout,   // [1,32]
                const float* __restrict__ bout,   // [1]
                float* __restrict__ out)          // [1024]
{
    const int lane = threadIdx.x & 31;
    const int wib  = threadIdx.x >> 5;
    const int b    = blockIdx.x * (blockDim.x >> 5) + wib;

    __shared__ float2 sbuf[4][2][32];   // [warp-in-block][double buffer][step]

    // Per-lane (= per hidden unit) constants
    const float w0 = Wg[2 * lane];
    const float w1 = Wg[2 * lane + 1];
    const float ag = 1.0f / (1.0f + expf(-tau_g[lane]));
    const float bg = __fsub_rn(1.0f, ag);
    const float as = 1.0f / (1.0f + expf(-tau_s[lane]));
    const float bs = __fsub_rn(1.0f, as);

    const float2* xp = reinterpret_cast<const float2*>(x) + (size_t)b * TT;

    float v = 0.0f, s = 0.0f, Vs = 0.0f, Ss = 0.0f;
    float acc = 0.0f, base = 0.0f;

    // Prime first buffer
    float2 nxt = xp[lane];
    sbuf[wib][0][lane] = nxt;
    __syncwarp();
    int cur = 0;

    for (int chunk = 0; chunk < 32; ++chunk) {
        // Prefetch next chunk early (hidden behind 32 compute steps)
        if (chunk + 1 < 32) nxt = xp[(chunk + 1) * 32 + lane];

        const float2* buf = sbuf[wib][cur];
        #pragma unroll
        for (int i = 0; i < 32; ++i) {
            float2 xv = buf[i];
            // gi = x0*w0 + x1*w1  (einsum over I=2), no contraction
            float gi = __fadd_rn(__fmul_rn(xv.x, w0), __fmul_rn(xv.y, w1));
            // v = ag*v + bg*gi - s   (left-to-right, V_TH = 1)
            v = __fsub_rn(__fadd_rn(__fmul_rn(ag, v), __fmul_rn(bg, gi)), s);
            // s = spike(v - 1) = (v > 1)
            s = (v > 1.0f) ? 1.0f : 0.0f;
            // V = as*V + bs*s - S
            Vs = __fsub_rn(__fadd_rn(__fmul_rn(as, Vs), __fmul_rn(bs, s)), Ss);
            Ss = (Vs > 1.0f) ? 1.0f : 0.0f;
            // Unconditional spike count (exact small int in fp32)
            acc += Ss;
        }

        if (chunk == DECISION_CHUNK - 1) base = acc;  // snapshot at t=768

        if (chunk + 1 < 32) sbuf[wib][cur ^ 1][lane] = nxt;
        __syncwarp();
        cur ^= 1;
    }

    // out[b] = sum_h (acc_h - base_h) * Wout[h] + bout[0]
    float val = __fmul_rn(__fsub_rn(acc, base), Wout[lane]);
    #pragma unroll
    for (int off = 16; off; off >>= 1)
        val += __shfl_xor_sync(0xffffffffu, val, off);
    if (lane == 0) out[b] = val + bout[0];
}

extern "C" void kernel_launch(void* const* d_in, const int* in_sizes, int n_in,
                              void* d_out, int out_size) {
    const float* x    = (const float*)d_in[0];
    const float* Wg   = (const float*)d_in[1];
    const float* taug = (const float*)d_in[2];
    const float* taus = (const float*)d_in[3];
    const float* Wout = (const float*)d_in[4];
    const float* bout = (const float*)d_in[5];
    float* out = (float*)d_out;

    // 1024 warps total: 128 threads (4 warps) per block, 256 blocks
    snn_kernel<<<NB / 4, 128>>>(x, Wg, taug, taus, Wout, bout, out);
}

// round 2
// speedup vs baseline: 1.0014x; 1.0014x over previous
#include <cuda_runtime.h>

// SNN recurrence: B=1024, T=1024, H=32, I=2.
// Mapping: one warp per 2 batches; lane = hidden unit; each thread runs the
// chains of TWO batches packed in f32x2 (mul.rn.f32x2 / add.rn.f32x2 round
// identically to scalar .rn ops, so the trajectory stays bit-exact vs the
// reference-order scalar version that scored rel_err = 0.0).
//
// Spikes carried negated (-1/0) so "x - s" becomes a packed add (bit-identical
// incl. signed-zero cases). Spike-count accumulation only in the decision
// window (chunks 24..31 <=> t >= 768).

#define TT 1024
#define V_TH 1.0f

union F2U { float2 f; unsigned long long u; };

__device__ __forceinline__ float2 mul2(float2 a, float2 b) {
    F2U A, B, R; A.f = a; B.f = b;
    asm("mul.rn.f32x2 %0, %1, %2;" : "=l"(R.u) : "l"(A.u), "l"(B.u));
    return R.f;
}
__device__ __forceinline__ float2 add2(float2 a, float2 b) {
    F2U A, B, R; A.f = a; B.f = b;
    asm("add.rn.f32x2 %0, %1, %2;" : "=l"(R.u) : "l"(A.u), "l"(B.u));
    return R.f;
}

struct State {
    float2 v, V;        // group / soma membrane potentials (2 batches)
    float2 sneg, Sneg;  // negated spikes: -1.0 or 0.0
    float2 accn;        // negated spike count
};

template <bool ACC>
__device__ __forceinline__ void run_chunk(State& st, const float4* __restrict__ buf,
                                          float2 W0, float2 W1, float2 AG, float2 BG,
                                          float2 AS, float bs) {
    #pragma unroll
    for (int i = 0; i < 32; ++i) {
        float4 q = buf[i];
        float2 X0 = make_float2(q.x, q.y);   // x[:,t,0] for (b0,b1)
        float2 X1 = make_float2(q.z, q.w);   // x[:,t,1] for (b0,b1)

        // gi = x0*w0 + x1*w1 ; u = (1-ag)*gi   (reference evaluation order)
        float2 gi = add2(mul2(X0, W0), mul2(X1, W1));
        float2 u  = mul2(BG, gi);

        // v = (ag*v + u) - s_prev   (sub as add of negated spike: bit-identical)
        st.v = add2(add2(mul2(AG, st.v), u), st.sneg);

        // group spikes + soma input m = bs*s  (select(p,bs,+0) == bs*s exactly)
        float2 m;
        st.sneg.x = (st.v.x > V_TH) ? -1.0f : 0.0f;
        st.sneg.y = (st.v.y > V_TH) ? -1.0f : 0.0f;
        m.x       = (st.v.x > V_TH) ? bs    : 0.0f;
        m.y       = (st.v.y > V_TH) ? bs    : 0.0f;

        // V = (as*V + m) - S_prev
        st.V = add2(add2(mul2(AS, st.V), m), st.Sneg);
        st.Sneg.x = (st.V.x > V_TH) ? -1.0f : 0.0f;
        st.Sneg.y = (st.V.y > V_TH) ? -1.0f : 0.0f;

        if (ACC) st.accn = add2(st.accn, st.Sneg);
    }
}

__global__ __launch_bounds__(128, 8)
void snn_kernel(const float* __restrict__ x,
                const float* __restrict__ Wg,     // [32,2]
                const float* __restrict__ tau_g,  // [32]
                const float* __restrict__ tau_s,  // [32]
                const float* __restrict__ Wout,   // [32]
                const float* __restrict__ bout,   // [1]
                float* __restrict__ out)          // [1024]
{
    const int lane = threadIdx.x & 31;
    const int wib  = threadIdx.x >> 5;
    const int gw   = blockIdx.x * 4 + wib;   // global warp 0..511
    const int b0   = gw * 2;                 // this warp's two batches

    __shared__ float4 sbuf[4][2][32];        // [warp][double buffer][step]

    const float w0 = Wg[2 * lane];
    const float w1 = Wg[2 * lane + 1];
    const float ag = 1.0f / (1.0f + expf(-tau_g[lane]));
    const float bg = 1.0f - ag;
    const float as = 1.0f / (1.0f + expf(-tau_s[lane]));
    const float bs = 1.0f - as;

    const float2 W0 = make_float2(w0, w0), W1 = make_float2(w1, w1);
    const float2 AG = make_float2(ag, ag), BG = make_float2(bg, bg);
    const float2 AS = make_float2(as, as);

    const float2* xp0 = reinterpret_cast<const float2*>(x) + (size_t)b0 * TT;
    const float2* xp1 = xp0 + TT;

    State st;
    st.v = st.V = st.sneg = st.Sneg = st.accn = make_float2(0.0f, 0.0f);

    // Prime buffer 0
    float2 g0 = xp0[lane], g1 = xp1[lane];
    sbuf[wib][0][lane] = make_float4(g0.x, g1.x, g0.y, g1.y);
    __syncwarp();
    int cur = 0;

    #pragma unroll 1
    for (int chunk = 0; chunk < 24; ++chunk) {
        g0 = xp0[(chunk + 1) * 32 + lane];
        g1 = xp1[(chunk + 1) * 32 + lane];
        run_chunk<false>(st, sbuf[wib][cur], W0, W1, AG, BG, AS, bs);
        sbuf[wib][cur ^ 1][lane] = make_float4(g0.x, g1.x, g0.y, g1.y);
        __syncwarp();
        cur ^= 1;
    }
    #pragma unroll 1
    for (int chunk = 24; chunk < 32; ++chunk) {
        if (chunk + 1 < 32) {
            g0 = xp0[(chunk + 1) * 32 + lane];
            g1 = xp1[(chunk + 1) * 32 + lane];
        }
        run_chunk<true>(st, sbuf[wib][cur], W0, W1, AG, BG, AS, bs);
        if (chunk + 1 < 32) {
            sbuf[wib][cur ^ 1][lane] = make_float4(g0.x, g1.x, g0.y, g1.y);
        }
        __syncwarp();
        cur ^= 1;
    }

    // Readout: out[b] = sum_h cnt_h * Wout[h] + bout  (same tree order per batch
    // as the rel_err=0.0 kernel)
    const float wl = Wout[lane];
    float2 val = make_float2(-st.accn.x * wl, -st.accn.y * wl);
    #pragma unroll
    for (int off = 16; off; off >>= 1) {
        val.x += __shfl_xor_sync(0xffffffffu, val.x, off);
        val.y += __shfl_xor_sync(0xffffffffu, val.y, off);
    }
    if (lane == 0) {
        const float bb = bout[0];
        out[b0]     = val.x + bb;
        out[b0 + 1] = val.y + bb;
    }
}

extern "C" void kernel_launch(void* const* d_in, const int* in_sizes, int n_in,
                              void* d_out, int out_size) {
    const float* x    = (const float*)d_in[0];
    const float* Wg   = (const float*)d_in[1];
    const float* taug = (const float*)d_in[2];
    const float* taus = (const float*)d_in[3];
    const float* Wout = (const float*)d_in[4];
    const float* bout = (const float*)d_in[5];
    float* out = (float*)d_out;

    // 512 warps (2 batches each): 128 blocks x 128 threads
    snn_kernel<<<128, 128>>>(x, Wg, taug, taus, Wout, bout, out);
}